// round 15
// baseline (speedup 1.0000x reference)
#include <cuda_runtime.h>
#include <cuda_fp16.h>
#include <cstdint>
#include <math.h>

#define BB   32
#define SEQ  577
#define DIM  768
#define QKVD 2304
#define ROWS (BB * SEQ)      // 18464
#define SPAD 640

// ---------------- scratch ----------------
__device__ __half g_xh  [(size_t)ROWS * DIM];
__device__ __half g_wqh [(size_t)QKVD * DIM];
__device__ __half g_wph [(size_t)DIM * DIM];
__device__ __half g_qkvh[(size_t)ROWS * QKVD];
__device__ float  g_s   [(size_t)BB * SEQ * SPAD];
__device__ __half g_p   [(size_t)BB * SEQ * SPAD];
__device__ __half g_vt  [(size_t)BB * DIM * SPAD];
__device__ __half g_yt  [(size_t)BB * DIM * SEQ];

// ---------------- helpers ----------------
__device__ __forceinline__ uint32_t smem_u32(const void* p) {
    uint32_t a;
    asm("{ .reg .u64 t; cvta.to.shared.u64 t, %1; cvt.u32.u64 %0, t; }"
        : "=r"(a) : "l"(p));
    return a;
}
__device__ __forceinline__ void cpa16(uint32_t dst, const __half* src, bool ok) {
    int sz = ok ? 16 : 0;
    asm volatile("cp.async.cg.shared.global [%0], [%1], 16, %2;"
                 :: "r"(dst), "l"(src), "r"(sz));
}
__device__ __forceinline__ void ldsm4(uint32_t a, uint32_t* r) {
    asm volatile("ldmatrix.sync.aligned.m8n8.x4.shared.b16 {%0,%1,%2,%3}, [%4];"
                 : "=r"(r[0]), "=r"(r[1]), "=r"(r[2]), "=r"(r[3]) : "r"(a));
}
__device__ __forceinline__ void mma16(float* d, const uint32_t* a, const uint32_t* b) {
    asm volatile(
        "mma.sync.aligned.m16n8k16.row.col.f32.f16.f16.f32 "
        "{%0,%1,%2,%3}, {%4,%5,%6,%7}, {%8,%9}, {%0,%1,%2,%3};"
        : "+f"(d[0]), "+f"(d[1]), "+f"(d[2]), "+f"(d[3])
        : "r"(a[0]), "r"(a[1]), "r"(a[2]), "r"(a[3]), "r"(b[0]), "r"(b[1]));
}

// ---------------- tiling ----------------
#define STAGE_A 16384
#define STAGE_BYTES 32768
#define NSTAGE 3
#define TC_SMEM (NSTAGE * STAGE_BYTES)   // 96KB -> 2 CTAs/SM

__device__ __forceinline__ void fill_stage_Aop(
    const __half* __restrict__ A, int M, int lda, int m0, int k0,
    uint32_t st, int tid)
{
    const int q = tid & 7;
    const int r0 = tid >> 3;
    const int swq = (q ^ (r0 & 7)) << 4;
#pragma unroll
    for (int p = 0; p < 4; p++) {
        const int r = r0 + p * 32;
        const int gr = m0 + r;
        const bool ok = gr < M;
        cpa16(st + r * 128 + swq, A + (long)(ok ? gr : 0) * lda + k0 + q * 8, ok);
    }
}
__device__ __forceinline__ void fill_stage_Bop(
    const __half* __restrict__ B, int N, int ldb, int n0, int k0,
    uint32_t st, int tid)
{
    const int q = tid & 7;
    const int r0 = tid >> 3;
    const int swq = (q ^ (r0 & 7)) << 4;
#pragma unroll
    for (int p = 0; p < 4; p++) {
        const int r = r0 + p * 32;
        const int gr = n0 + r;
        const bool ok = gr < N;
        cpa16(st + STAGE_A + r * 128 + swq,
              B + (long)(ok ? gr : 0) * ldb + k0 + q * 8, ok);
    }
}

// ---------------------------------------------------------------------------
// NT GEMM, fp16 in, fp32 accum. outHalf=0: C float (+bias); 1: C half.
// fuseV: columns n >= 1536 are written transposed into vtOut.
// Refill split across s=0 (A half) and s=1 (B half + commit) to avoid an
// 8-deep LDGSTS burst stalling the issuing warp's ldsm stream.
// ---------------------------------------------------------------------------
__global__ __launch_bounds__(256, 2) void gemm_h(
    const __half* __restrict__ A, const __half* __restrict__ B,
    void* __restrict__ Cv, const float* __restrict__ bias,
    int M, int N, int K, int lda, int ldb, int ldc,
    long sA, long sB, long sC, float alpha, int outHalf,
    int fuseV, __half* __restrict__ vtOut)
{
    extern __shared__ char smem[];
    const uint32_t sb = smem_u32(smem);
    const int tid = threadIdx.x;
    const int wid = tid >> 5, lane = tid & 31;
    const int wm = wid & 1, wn = wid >> 1;      // warp tile 64(m) x 32(n)

    const int bz = blockIdx.z;
    A += (long)bz * sA;  B += (long)bz * sB;
    const int m0 = blockIdx.y * 128;
    const int n0 = blockIdx.x * 128;
    const int KT = K >> 6;

    const int a_row = lane & 15;
    const int a_co  = lane >> 4;
    const uint32_t a_base = (uint32_t)((wm * 64 + a_row) * 128 +
                                       ((a_co ^ (a_row & 7)) << 4));
    const int b_rowoff = ((lane >> 4) & 1) * 8 + (lane & 7);
    const int b_co     = (lane >> 3) & 1;
    const uint32_t b_base = (uint32_t)(STAGE_A + (wn * 32 + b_rowoff) * 128 +
                                       ((b_co ^ (b_rowoff & 7)) << 4));

    float acc[4][4][4];
#pragma unroll
    for (int i = 0; i < 4; i++)
#pragma unroll
        for (int j = 0; j < 4; j++)
#pragma unroll
            for (int r = 0; r < 4; r++) acc[i][j][r] = 0.f;

    fill_stage_Aop(A, M, lda, m0, 0, sb, tid);
    fill_stage_Bop(B, N, ldb, n0, 0, sb, tid);
    asm volatile("cp.async.commit_group;" ::: "memory");
    if (KT > 1) {
        fill_stage_Aop(A, M, lda, m0, 64, sb + STAGE_BYTES, tid);
        fill_stage_Bop(B, N, ldb, n0, 64, sb + STAGE_BYTES, tid);
    }
    asm volatile("cp.async.commit_group;" ::: "memory");

    for (int kt = 0; kt < KT; kt++) {
        asm volatile("cp.async.wait_group 1;" ::: "memory");
        __syncthreads();

        const uint32_t st = sb + (kt % NSTAGE) * STAGE_BYTES;
        const int fs = kt + 2;
        const uint32_t fst = sb + (fs % NSTAGE) * STAGE_BYTES;

        uint32_t bf[2][2][4];                    // [buf][np][regs]
        ldsm4(st + b_base,        bf[0][0]);
        ldsm4(st + b_base + 2048, bf[0][1]);

#pragma unroll
        for (int s = 0; s < 4; s++) {
            const int cur = s & 1, nxt = cur ^ 1;
            if (s < 3) {                         // prefetch B frags for s+1
                const uint32_t kswn = (uint32_t)(2 * (s + 1)) << 4;
                const uint32_t bb2 = st + (b_base ^ kswn);
                ldsm4(bb2,        bf[nxt][0]);
                ldsm4(bb2 + 2048, bf[nxt][1]);
            }
            const uint32_t ksw = (uint32_t)(2 * s) << 4;
            const uint32_t ba = st + (a_base ^ ksw);
#pragma unroll
            for (int mtp = 0; mtp < 2; mtp++) {  // A in pairs (8 live regs)
                uint32_t af[2][4];
                ldsm4(ba + (2 * mtp) * 2048,     af[0]);
                ldsm4(ba + (2 * mtp + 1) * 2048, af[1]);
#pragma unroll
                for (int mi = 0; mi < 2; mi++) {
                    const int mt = 2 * mtp + mi;
#pragma unroll
                    for (int nt = 0; nt < 4; nt++)
                        mma16(acc[mt][nt], af[mi], &bf[cur][nt >> 1][(nt & 1) * 2]);
                }
            }
            if (s == 0) {                        // refill A half
                if (fs < KT) fill_stage_Aop(A, M, lda, m0, fs * 64, fst, tid);
            } else if (s == 1) {                 // refill B half + commit
                if (fs < KT) fill_stage_Bop(B, N, ldb, n0, fs * 64, fst, tid);
                asm volatile("cp.async.commit_group;" ::: "memory");
            }
        }
    }

    // epilogue
    const int r4 = lane >> 2, cp2 = (lane & 3) * 2;
    if (outHalf) {
        __half* C = (__half*)Cv + (long)bz * sC;
        const bool vec = ((ldc & 1) == 0);       // ldc odd -> scalar stores
#pragma unroll
        for (int mt = 0; mt < 4; mt++)
#pragma unroll
            for (int half_ = 0; half_ < 2; half_++) {
                const int m = m0 + wm * 64 + mt * 16 + r4 + half_ * 8;
                if (m >= M) continue;
                const long base = (long)m * ldc;
#pragma unroll
                for (int nt = 0; nt < 4; nt++) {
                    const int n = n0 + wn * 32 + nt * 8 + cp2;
                    if (n >= N) continue;
                    const float v0 = acc[mt][nt][half_ * 2 + 0] * alpha;
                    const float v1 = acc[mt][nt][half_ * 2 + 1] * alpha;
                    if (fuseV && n >= 1536) {
                        const int b = m / SEQ;
                        const int kk = m - b * SEQ;
                        __half* dst = vtOut + (long)b * DIM * SPAD
                                            + (long)(n - 1536) * SPAD + kk;
                        dst[0]    = __float2half_rn(v0);
                        dst[SPAD] = __float2half_rn(v1);
                    } else if (vec && (n + 1 < N)) {
                        *(__half2*)(C + base + n) = __floats2half2_rn(v0, v1);
                    } else {
                        C[base + n] = __float2half_rn(v0);
                        if (n + 1 < N) C[base + n + 1] = __float2half_rn(v1);
                    }
                }
            }
    } else {
        float* C = (float*)Cv + (long)bz * sC;
#pragma unroll
        for (int mt = 0; mt < 4; mt++)
#pragma unroll
            for (int half_ = 0; half_ < 2; half_++) {
                const int m = m0 + wm * 64 + mt * 16 + r4 + half_ * 8;
                if (m >= M) continue;
                const long base = (long)m * ldc;
#pragma unroll
                for (int nt = 0; nt < 4; nt++) {
                    const int n = n0 + wn * 32 + nt * 8 + cp2;
                    if (n >= N) continue;
                    float v0 = acc[mt][nt][half_ * 2 + 0] * alpha;
                    float v1 = acc[mt][nt][half_ * 2 + 1] * alpha;
                    if (bias) {
                        v0 += bias[n];
                        if (n + 1 < N) v1 += bias[n + 1];
                    }
                    if (((ldc & 1) == 0) && (n + 1 < N)) {
                        *(float2*)(C + base + n) = make_float2(v0, v1);
                    } else {
                        C[base + n] = v0;
                        if (n + 1 < N) C[base + n + 1] = v1;
                    }
                }
            }
    }
}

// ---------------- merged prologue: f2h x3 + vt pad zero ----------------
#define N1 ((long)ROWS * DIM / 4)
#define N2 ((long)QKVD * DIM / 4)
#define N3 ((long)DIM * DIM / 4)
#define N4 ((long)BB * DIM * 8)

__device__ __forceinline__ void cvt4(const float* __restrict__ in,
                                     __half* __restrict__ out, long i) {
    const float4 v = *(const float4*)(in + i * 4);
    *(__half2*)(out + i * 4)     = __floats2half2_rn(v.x, v.y);
    *(__half2*)(out + i * 4 + 2) = __floats2half2_rn(v.z, v.w);
}

__global__ void prologue_kernel(const float* __restrict__ x,
                                const float* __restrict__ wq,
                                const float* __restrict__ wp,
                                __half* __restrict__ xh,
                                __half* __restrict__ wqh,
                                __half* __restrict__ wph,
                                __half* __restrict__ vt) {
    long i = (long)blockIdx.x * blockDim.x + threadIdx.x;
    if (i < N1) { cvt4(x, xh, i); return; }
    i -= N1;
    if (i < N2) { cvt4(wq, wqh, i); return; }
    i -= N2;
    if (i < N3) { cvt4(wp, wph, i); return; }
    i -= N3;
    if (i < N4) {
        const long rc = i >> 3, j = i & 7;       // pad k in [576,640)
        *(float4*)(vt + rc * SPAD + 576 + j * 8) =
            make_float4(0.f, 0.f, 0.f, 0.f);
    }
}

// ---------------- softmax: one warp per row, barrier-free -------------------
__global__ __launch_bounds__(256) void softmax_kernel(
    const float* __restrict__ S, __half* __restrict__ P, float* __restrict__ tok)
{
    const int row  = (blockIdx.x << 3) | (threadIdx.x >> 5);
    const int lane = threadIdx.x & 31;
    const float* p = S + (long)row * SPAD;
    __half* o = P + (long)row * SPAD;

    float4 v[5];
    float m = -1e30f;
#pragma unroll
    for (int j = 0; j < 5; j++) {
        const int c0 = (lane + (j << 5)) << 2;
        float4 t = *(const float4*)(p + c0);
        t.x = (c0 + 0 < SEQ) ? t.x : -1e30f;
        t.y = (c0 + 1 < SEQ) ? t.y : -1e30f;
        t.z = (c0 + 2 < SEQ) ? t.z : -1e30f;
        t.w = (c0 + 3 < SEQ) ? t.w : -1e30f;
        v[j] = t;
        m = fmaxf(m, fmaxf(fmaxf(t.x, t.y), fmaxf(t.z, t.w)));
    }
#pragma unroll
    for (int off = 16; off > 0; off >>= 1)
        m = fmaxf(m, __shfl_xor_sync(0xFFFFFFFFu, m, off));

    float sum = 0.f;
#pragma unroll
    for (int j = 0; j < 5; j++) {
        v[j].x = __expf(v[j].x - m);
        v[j].y = __expf(v[j].y - m);
        v[j].z = __expf(v[j].z - m);
        v[j].w = __expf(v[j].w - m);
        sum += (v[j].x + v[j].y) + (v[j].z + v[j].w);
    }
#pragma unroll
    for (int off = 16; off > 0; off >>= 1)
        sum += __shfl_xor_sync(0xFFFFFFFFu, sum, off);
    const float inv = 1.0f / sum;

#pragma unroll
    for (int j = 0; j < 5; j++) {
        const int c0 = (lane + (j << 5)) << 2;
        *(__half2*)(o + c0)     = __floats2half2_rn(v[j].x * inv, v[j].y * inv);
        *(__half2*)(o + c0 + 2) = __floats2half2_rn(v[j].z * inv, v[j].w * inv);
    }

    if ((row % SEQ) == 0) {                      // token-attn extraction
        const int b = row / SEQ;
        float* t = tok + (long)b * (SEQ - 1);
#pragma unroll
        for (int j = 0; j < 5; j++) {
            const int c0 = (lane + (j << 5)) << 2;
            const float xs[4] = {v[j].x * inv, v[j].y * inv,
                                 v[j].z * inv, v[j].w * inv};
#pragma unroll
            for (int q = 0; q < 4; q++) {
                const int c = c0 + q;
                if (c >= 1 && c < SEQ) t[c - 1] = xs[q];
            }
        }
    }
}

// ---------------------------------------------------------------------------
extern "C" void kernel_launch(void* const* d_in, const int* in_sizes, int n_in,
                              void* d_out, int out_size)
{
    const float* x      = (const float*)d_in[0];
    const float* w_qkv  = (const float*)d_in[1];
    const float* w_proj = (const float*)d_in[2];
    const float* b_proj = (const float*)d_in[3];
    float* out = (float*)d_out;
    float* tok = out + (size_t)ROWS * DIM;

    __half *xh, *wqh, *wph, *qkvh, *p, *vt, *yt;
    float *s;
    cudaGetSymbolAddress((void**)&xh,   g_xh);
    cudaGetSymbolAddress((void**)&wqh,  g_wqh);
    cudaGetSymbolAddress((void**)&wph,  g_wph);
    cudaGetSymbolAddress((void**)&qkvh, g_qkvh);
    cudaGetSymbolAddress((void**)&s,    g_s);
    cudaGetSymbolAddress((void**)&p,    g_p);
    cudaGetSymbolAddress((void**)&vt,   g_vt);
    cudaGetSymbolAddress((void**)&yt,   g_yt);

    cudaFuncSetAttribute(gemm_h, cudaFuncAttributeMaxDynamicSharedMemorySize, TC_SMEM);

    const float scale = 1.0f / sqrtf((float)DIM);

    // 0) merged prologue
    {
        const long total = N1 + N2 + N3 + N4;
        prologue_kernel<<<(int)((total + 255) / 256), 256>>>(
            x, w_qkv, w_proj, xh, wqh, wph, vt);
    }

    // 1) QKV (half out; V columns written transposed into vt)
    gemm_h<<<dim3(QKVD / 128, (ROWS + 127) / 128, 1), 256, TC_SMEM>>>(
        xh, wqh, qkvh, nullptr, ROWS, QKVD, DIM, DIM, DIM, QKVD,
        0, 0, 0, 1.0f, 1, 1, vt);

    // 2) S = scale * Q K^T (float out, ldc=SPAD even)
    gemm_h<<<dim3((SEQ + 127) / 128, (SEQ + 127) / 128, BB), 256, TC_SMEM>>>(
        qkvh, qkvh + DIM, s, nullptr, SEQ, SEQ, DIM, QKVD, QKVD, SPAD,
        (long)SEQ * QKVD, (long)SEQ * QKVD, (long)SEQ * SPAD, scale, 0, 0, nullptr);

    // 3) softmax -> fp16 P
    softmax_kernel<<<ROWS / 8, 256>>>(s, p, tok);

    // 4) yt = Vt @ P^T (half out, ldc=SEQ odd -> scalar epilogue path)
    gemm_h<<<dim3((SEQ + 127) / 128, DIM / 128, BB), 256, TC_SMEM>>>(
        vt, p, yt, nullptr, DIM, SEQ, SPAD, SPAD, SPAD, SEQ,
        (long)DIM * SPAD, (long)SEQ * SPAD, (long)DIM * SEQ, 1.0f, 1, 0, nullptr);

    // 5) out = Y2 @ Wproj^T + bias (float out)
    gemm_h<<<dim3(DIM / 128, (ROWS + 127) / 128, 1), 256, TC_SMEM>>>(
        yt, wph, out, b_proj, ROWS, DIM, DIM, DIM, DIM, DIM,
        0, 0, 0, 1.0f, 0, 0, nullptr);
}

// round 16
// speedup vs baseline: 1.5380x; 1.5380x over previous
#include <cuda_runtime.h>
#include <cuda_fp16.h>
#include <cstdint>
#include <math.h>

#define BB   32
#define SEQ  577
#define DIM  768
#define QKVD 2304
#define ROWS (BB * SEQ)      // 18464
#define SPAD 640

// ---------------- scratch ----------------
__device__ __half g_xh  [(size_t)ROWS * DIM];
__device__ __half g_wqh [(size_t)QKVD * DIM];
__device__ __half g_wph [(size_t)DIM * DIM];
__device__ __half g_qkvh[(size_t)ROWS * QKVD];
__device__ float  g_s   [(size_t)BB * SEQ * SPAD];
__device__ __half g_p   [(size_t)BB * SEQ * SPAD];
__device__ __half g_vt  [(size_t)BB * DIM * SPAD];
__device__ __half g_yt  [(size_t)BB * DIM * SEQ];

// ---------------- helpers ----------------
__device__ __forceinline__ uint32_t smem_u32(const void* p) {
    uint32_t a;
    asm("{ .reg .u64 t; cvta.to.shared.u64 t, %1; cvt.u32.u64 %0, t; }"
        : "=r"(a) : "l"(p));
    return a;
}
__device__ __forceinline__ void cpa16(uint32_t dst, const __half* src, bool ok) {
    int sz = ok ? 16 : 0;
    asm volatile("cp.async.cg.shared.global [%0], [%1], 16, %2;"
                 :: "r"(dst), "l"(src), "r"(sz));
}
__device__ __forceinline__ void ldsm4(uint32_t a, uint32_t* r) {
    asm volatile("ldmatrix.sync.aligned.m8n8.x4.shared.b16 {%0,%1,%2,%3}, [%4];"
                 : "=r"(r[0]), "=r"(r[1]), "=r"(r[2]), "=r"(r[3]) : "r"(a));
}
__device__ __forceinline__ void mma16(float* d, const uint32_t* a, const uint32_t* b) {
    asm volatile(
        "mma.sync.aligned.m16n8k16.row.col.f32.f16.f16.f32 "
        "{%0,%1,%2,%3}, {%4,%5,%6,%7}, {%8,%9}, {%0,%1,%2,%3};"
        : "+f"(d[0]), "+f"(d[1]), "+f"(d[2]), "+f"(d[3])
        : "r"(a[0]), "r"(a[1]), "r"(a[2]), "r"(a[3]), "r"(b[0]), "r"(b[1]));
}

// ---------------- tiling ----------------
#define STAGE_A 16384
#define STAGE_BYTES 32768
#define NSTAGE 3
#define TC_SMEM (NSTAGE * STAGE_BYTES)   // 96KB -> 2 CTAs/SM

__device__ __forceinline__ void fill_stage(
    const __half* __restrict__ A, const __half* __restrict__ B,
    int M, int N, int lda, int ldb, int m0, int n0, int k0,
    uint32_t st, int tid)
{
    const int q = tid & 7;
    const int r0 = tid >> 3;
    const int swq = (q ^ (r0 & 7)) << 4;
#pragma unroll
    for (int p = 0; p < 4; p++) {
        const int r = r0 + p * 32;
        {
            const int gr = m0 + r;
            const bool ok = gr < M;
            cpa16(st + r * 128 + swq, A + (long)(ok ? gr : 0) * lda + k0 + q * 8, ok);
        }
        {
            const int gr = n0 + r;
            const bool ok = gr < N;
            cpa16(st + STAGE_A + r * 128 + swq,
                  B + (long)(ok ? gr : 0) * ldb + k0 + q * 8, ok);
        }
    }
}

// ---------------------------------------------------------------------------
// NT GEMM, fp16 in, fp32 accum. outHalf=0: C float (+bias); 1: C half.
// fuseV: columns n >= 1536 are written transposed into vtOut.
// ---------------------------------------------------------------------------
__global__ __launch_bounds__(256, 2) void gemm_h(
    const __half* __restrict__ A, const __half* __restrict__ B,
    void* __restrict__ Cv, const float* __restrict__ bias,
    int M, int N, int K, int lda, int ldb, int ldc,
    long sA, long sB, long sC, float alpha, int outHalf,
    int fuseV, __half* __restrict__ vtOut)
{
    extern __shared__ char smem[];
    const uint32_t sb = smem_u32(smem);
    const int tid = threadIdx.x;
    const int wid = tid >> 5, lane = tid & 31;
    const int wm = wid & 1, wn = wid >> 1;      // warp tile 64(m) x 32(n)

    const int bz = blockIdx.z;
    A += (long)bz * sA;  B += (long)bz * sB;
    const int m0 = blockIdx.y * 128;
    const int n0 = blockIdx.x * 128;
    const int KT = K >> 6;

    const int a_row = lane & 15;
    const int a_co  = lane >> 4;
    const uint32_t a_base = (uint32_t)((wm * 64 + a_row) * 128 +
                                       ((a_co ^ (a_row & 7)) << 4));
    const int b_rowoff = ((lane >> 4) & 1) * 8 + (lane & 7);
    const int b_co     = (lane >> 3) & 1;
    const uint32_t b_base = (uint32_t)(STAGE_A + (wn * 32 + b_rowoff) * 128 +
                                       ((b_co ^ (b_rowoff & 7)) << 4));

    float acc[4][4][4];
#pragma unroll
    for (int i = 0; i < 4; i++)
#pragma unroll
        for (int j = 0; j < 4; j++)
#pragma unroll
            for (int r = 0; r < 4; r++) acc[i][j][r] = 0.f;

    fill_stage(A, B, M, N, lda, ldb, m0, n0, 0, sb, tid);
    asm volatile("cp.async.commit_group;" ::: "memory");
    if (KT > 1)
        fill_stage(A, B, M, N, lda, ldb, m0, n0, 64, sb + STAGE_BYTES, tid);
    asm volatile("cp.async.commit_group;" ::: "memory");

    for (int kt = 0; kt < KT; kt++) {
        asm volatile("cp.async.wait_group 1;" ::: "memory");
        __syncthreads();

        const uint32_t st = sb + (kt % NSTAGE) * STAGE_BYTES;

        uint32_t bf[2][2][4];                    // [buf][np][regs]
        ldsm4(st + b_base,        bf[0][0]);
        ldsm4(st + b_base + 2048, bf[0][1]);

#pragma unroll
        for (int s = 0; s < 4; s++) {
            const int cur = s & 1, nxt = cur ^ 1;
            if (s < 3) {                         // prefetch B for s+1
                const uint32_t kswn = (uint32_t)(2 * (s + 1)) << 4;
                const uint32_t bb2 = st + (b_base ^ kswn);
                ldsm4(bb2,        bf[nxt][0]);
                ldsm4(bb2 + 2048, bf[nxt][1]);
            }
            const uint32_t ksw = (uint32_t)(2 * s) << 4;
            const uint32_t ba = st + (a_base ^ ksw);
#pragma unroll
            for (int mtp = 0; mtp < 2; mtp++) {  // A in pairs (8 live regs)
                uint32_t af[2][4];
                ldsm4(ba + (2 * mtp) * 2048,     af[0]);
                ldsm4(ba + (2 * mtp + 1) * 2048, af[1]);
#pragma unroll
                for (int mi = 0; mi < 2; mi++) {
                    const int mt = 2 * mtp + mi;
#pragma unroll
                    for (int nt = 0; nt < 4; nt++)
                        mma16(acc[mt][nt], af[mi], &bf[cur][nt >> 1][(nt & 1) * 2]);
                }
            }
            if (s == 0) {                        // refill while s=1..3 compute
                const int fs = kt + 2;
                if (fs < KT)
                    fill_stage(A, B, M, N, lda, ldb, m0, n0, fs * 64,
                               sb + (fs % NSTAGE) * STAGE_BYTES, tid);
                asm volatile("cp.async.commit_group;" ::: "memory");
            }
        }
    }

    // epilogue
    const int r4 = lane >> 2, cp2 = (lane & 3) * 2;
    if (outHalf) {
        __half* C = (__half*)Cv + (long)bz * sC;
        const bool vec = ((ldc & 1) == 0);       // ldc odd -> scalar stores
#pragma unroll
        for (int mt = 0; mt < 4; mt++)
#pragma unroll
            for (int half_ = 0; half_ < 2; half_++) {
                const int m = m0 + wm * 64 + mt * 16 + r4 + half_ * 8;
                if (m >= M) continue;
                const long base = (long)m * ldc;
#pragma unroll
                for (int nt = 0; nt < 4; nt++) {
                    const int n = n0 + wn * 32 + nt * 8 + cp2;
                    if (n >= N) continue;
                    const float v0 = acc[mt][nt][half_ * 2 + 0] * alpha;
                    const float v1 = acc[mt][nt][half_ * 2 + 1] * alpha;
                    if (fuseV && n >= 1536) {
                        const int b = m / SEQ;
                        const int kk = m - b * SEQ;
                        __half* dst = vtOut + (long)b * DIM * SPAD
                                            + (long)(n - 1536) * SPAD + kk;
                        dst[0]    = __float2half_rn(v0);
                        dst[SPAD] = __float2half_rn(v1);
                    } else if (vec && (n + 1 < N)) {
                        *(__half2*)(C + base + n) = __floats2half2_rn(v0, v1);
                    } else {
                        C[base + n] = __float2half_rn(v0);
                        if (n + 1 < N) C[base + n + 1] = __float2half_rn(v1);
                    }
                }
            }
    } else {
        float* C = (float*)Cv + (long)bz * sC;
#pragma unroll
        for (int mt = 0; mt < 4; mt++)
#pragma unroll
            for (int half_ = 0; half_ < 2; half_++) {
                const int m = m0 + wm * 64 + mt * 16 + r4 + half_ * 8;
                if (m >= M) continue;
                const long base = (long)m * ldc;
#pragma unroll
                for (int nt = 0; nt < 4; nt++) {
                    const int n = n0 + wn * 32 + nt * 8 + cp2;
                    if (n >= N) continue;
                    float v0 = acc[mt][nt][half_ * 2 + 0] * alpha;
                    float v1 = acc[mt][nt][half_ * 2 + 1] * alpha;
                    if (bias) {
                        v0 += bias[n];
                        if (n + 1 < N) v1 += bias[n + 1];
                    }
                    if (((ldc & 1) == 0) && (n + 1 < N)) {
                        *(float2*)(C + base + n) = make_float2(v0, v1);
                    } else {
                        C[base + n] = v0;
                        if (n + 1 < N) C[base + n + 1] = v1;
                    }
                }
            }
    }
}

// ---------------- merged prologue: f2h x3 + vt pad zero ----------------
#define N1 ((long)ROWS * DIM / 4)
#define N2 ((long)QKVD * DIM / 4)
#define N3 ((long)DIM * DIM / 4)
#define N4 ((long)BB * DIM * 8)

__device__ __forceinline__ void cvt4(const float* __restrict__ in,
                                     __half* __restrict__ out, long i) {
    const float4 v = *(const float4*)(in + i * 4);
    *(__half2*)(out + i * 4)     = __floats2half2_rn(v.x, v.y);
    *(__half2*)(out + i * 4 + 2) = __floats2half2_rn(v.z, v.w);
}

__global__ void prologue_kernel(const float* __restrict__ x,
                                const float* __restrict__ wq,
                                const float* __restrict__ wp,
                                __half* __restrict__ xh,
                                __half* __restrict__ wqh,
                                __half* __restrict__ wph,
                                __half* __restrict__ vt) {
    long i = (long)blockIdx.x * blockDim.x + threadIdx.x;
    if (i < N1) { cvt4(x, xh, i); return; }
    i -= N1;
    if (i < N2) { cvt4(wq, wqh, i); return; }
    i -= N2;
    if (i < N3) { cvt4(wp, wph, i); return; }
    i -= N3;
    if (i < N4) {
        const long rc = i >> 3, j = i & 7;       // pad k in [576,640)
        *(float4*)(vt + rc * SPAD + 576 + j * 8) =
            make_float4(0.f, 0.f, 0.f, 0.f);
    }
}

// ---------------- softmax: one warp per row, barrier-free -------------------
__global__ __launch_bounds__(256) void softmax_kernel(
    const float* __restrict__ S, __half* __restrict__ P, float* __restrict__ tok)
{
    const int row  = (blockIdx.x << 3) | (threadIdx.x >> 5);
    const int lane = threadIdx.x & 31;
    const float* p = S + (long)row * SPAD;
    __half* o = P + (long)row * SPAD;

    float4 v[5];
    float m = -1e30f;
#pragma unroll
    for (int j = 0; j < 5; j++) {
        const int c0 = (lane + (j << 5)) << 2;
        float4 t = *(const float4*)(p + c0);
        t.x = (c0 + 0 < SEQ) ? t.x : -1e30f;
        t.y = (c0 + 1 < SEQ) ? t.y : -1e30f;
        t.z = (c0 + 2 < SEQ) ? t.z : -1e30f;
        t.w = (c0 + 3 < SEQ) ? t.w : -1e30f;
        v[j] = t;
        m = fmaxf(m, fmaxf(fmaxf(t.x, t.y), fmaxf(t.z, t.w)));
    }
#pragma unroll
    for (int off = 16; off > 0; off >>= 1)
        m = fmaxf(m, __shfl_xor_sync(0xFFFFFFFFu, m, off));

    float sum = 0.f;
#pragma unroll
    for (int j = 0; j < 5; j++) {
        v[j].x = __expf(v[j].x - m);
        v[j].y = __expf(v[j].y - m);
        v[j].z = __expf(v[j].z - m);
        v[j].w = __expf(v[j].w - m);
        sum += (v[j].x + v[j].y) + (v[j].z + v[j].w);
    }
#pragma unroll
    for (int off = 16; off > 0; off >>= 1)
        sum += __shfl_xor_sync(0xFFFFFFFFu, sum, off);
    const float inv = 1.0f / sum;

#pragma unroll
    for (int j = 0; j < 5; j++) {
        const int c0 = (lane + (j << 5)) << 2;
        *(__half2*)(o + c0)     = __floats2half2_rn(v[j].x * inv, v[j].y * inv);
        *(__half2*)(o + c0 + 2) = __floats2half2_rn(v[j].z * inv, v[j].w * inv);
    }

    if ((row % SEQ) == 0) {                      // token-attn extraction
        const int b = row / SEQ;
        float* t = tok + (long)b * (SEQ - 1);
#pragma unroll
        for (int j = 0; j < 5; j++) {
            const int c0 = (lane + (j << 5)) << 2;
            const float xs[4] = {v[j].x * inv, v[j].y * inv,
                                 v[j].z * inv, v[j].w * inv};
#pragma unroll
            for (int q = 0; q < 4; q++) {
                const int c = c0 + q;
                if (c >= 1 && c < SEQ) t[c - 1] = xs[q];
            }
        }
    }
}

// ---------------------------------------------------------------------------
extern "C" void kernel_launch(void* const* d_in, const int* in_sizes, int n_in,
                              void* d_out, int out_size)
{
    const float* x      = (const float*)d_in[0];
    const float* w_qkv  = (const float*)d_in[1];
    const float* w_proj = (const float*)d_in[2];
    const float* b_proj = (const float*)d_in[3];
    float* out = (float*)d_out;
    float* tok = out + (size_t)ROWS * DIM;

    __half *xh, *wqh, *wph, *qkvh, *p, *vt, *yt;
    float *s;
    cudaGetSymbolAddress((void**)&xh,   g_xh);
    cudaGetSymbolAddress((void**)&wqh,  g_wqh);
    cudaGetSymbolAddress((void**)&wph,  g_wph);
    cudaGetSymbolAddress((void**)&qkvh, g_qkvh);
    cudaGetSymbolAddress((void**)&s,    g_s);
    cudaGetSymbolAddress((void**)&p,    g_p);
    cudaGetSymbolAddress((void**)&vt,   g_vt);
    cudaGetSymbolAddress((void**)&yt,   g_yt);

    cudaFuncSetAttribute(gemm_h, cudaFuncAttributeMaxDynamicSharedMemorySize, TC_SMEM);

    const float scale = 1.0f / sqrtf((float)DIM);

    // 0) merged prologue
    {
        const long total = N1 + N2 + N3 + N4;
        prologue_kernel<<<(int)((total + 255) / 256), 256>>>(
            x, w_qkv, w_proj, xh, wqh, wph, vt);
    }

    // 1) QKV (half out; V columns written transposed into vt)
    gemm_h<<<dim3(QKVD / 128, (ROWS + 127) / 128, 1), 256, TC_SMEM>>>(
        xh, wqh, qkvh, nullptr, ROWS, QKVD, DIM, DIM, DIM, QKVD,
        0, 0, 0, 1.0f, 1, 1, vt);

    // 2) S = scale * Q K^T (float out, ldc=SPAD even)
    gemm_h<<<dim3((SEQ + 127) / 128, (SEQ + 127) / 128, BB), 256, TC_SMEM>>>(
        qkvh, qkvh + DIM, s, nullptr, SEQ, SEQ, DIM, QKVD, QKVD, SPAD,
        (long)SEQ * QKVD, (long)SEQ * QKVD, (long)SEQ * SPAD, scale, 0, 0, nullptr);

    // 3) softmax -> fp16 P
    softmax_kernel<<<ROWS / 8, 256>>>(s, p, tok);

    // 4) yt = Vt @ P^T (half out, ldc=SEQ odd -> scalar epilogue path)
    gemm_h<<<dim3((SEQ + 127) / 128, DIM / 128, BB), 256, TC_SMEM>>>(
        vt, p, yt, nullptr, DIM, SEQ, SPAD, SPAD, SPAD, SEQ,
        (long)DIM * SPAD, (long)SEQ * SPAD, (long)DIM * SEQ, 1.0f, 1, 0, nullptr);

    // 5) out = Y2 @ Wproj^T + bias (float out)
    gemm_h<<<dim3(DIM / 128, (ROWS + 127) / 128, 1), 256, TC_SMEM>>>(
        yt, wph, out, b_proj, ROWS, DIM, DIM, DIM, DIM, DIM,
        0, 0, 0, 1.0f, 0, 0, nullptr);
}

// round 17
// speedup vs baseline: 1.7282x; 1.1236x over previous
#include <cuda_runtime.h>
#include <cuda_fp16.h>
#include <cstdint>
#include <math.h>

#define BB   32
#define SEQ  577
#define DIM  768
#define QKVD 2304
#define ROWS (BB * SEQ)      // 18464
#define SPAD 640

// ---------------- scratch ----------------
__device__ __half g_xh  [(size_t)ROWS * DIM];
__device__ __half g_wqh [(size_t)QKVD * DIM];
__device__ __half g_wph [(size_t)DIM * DIM];
__device__ __half g_qkvh[(size_t)ROWS * QKVD];
__device__ float  g_s   [(size_t)BB * SEQ * SPAD];
__device__ __half g_p   [(size_t)BB * SEQ * SPAD];
__device__ __half g_vt  [(size_t)BB * DIM * SPAD];
__device__ __half g_yt  [(size_t)BB * DIM * SEQ];

// ---------------- helpers ----------------
__device__ __forceinline__ uint32_t smem_u32(const void* p) {
    uint32_t a;
    asm("{ .reg .u64 t; cvta.to.shared.u64 t, %1; cvt.u32.u64 %0, t; }"
        : "=r"(a) : "l"(p));
    return a;
}
__device__ __forceinline__ void cpa16(uint32_t dst, const __half* src, bool ok) {
    int sz = ok ? 16 : 0;
    asm volatile("cp.async.cg.shared.global [%0], [%1], 16, %2;"
                 :: "r"(dst), "l"(src), "r"(sz));
}
__device__ __forceinline__ void ldsm4(uint32_t a, uint32_t* r) {
    asm volatile("ldmatrix.sync.aligned.m8n8.x4.shared.b16 {%0,%1,%2,%3}, [%4];"
                 : "=r"(r[0]), "=r"(r[1]), "=r"(r[2]), "=r"(r[3]) : "r"(a));
}
__device__ __forceinline__ void mma16(float* d, const uint32_t* a, const uint32_t* b) {
    asm volatile(
        "mma.sync.aligned.m16n8k16.row.col.f32.f16.f16.f32 "
        "{%0,%1,%2,%3}, {%4,%5,%6,%7}, {%8,%9}, {%0,%1,%2,%3};"
        : "+f"(d[0]), "+f"(d[1]), "+f"(d[2]), "+f"(d[3])
        : "r"(a[0]), "r"(a[1]), "r"(a[2]), "r"(a[3]), "r"(b[0]), "r"(b[1]));
}

// ---------------- tiling ----------------
#define STAGE_A 16384
#define STAGE_BYTES 32768
#define NSTAGE 3
#define TC_SMEM (NSTAGE * STAGE_BYTES)   // 96KB -> 2 CTAs/SM

__device__ __forceinline__ void fill_stage(
    const __half* __restrict__ A, const __half* __restrict__ B,
    int M, int N, int lda, int ldb, int m0, int n0, int k0,
    uint32_t st, int tid)
{
    const int q = tid & 7;
    const int r0 = tid >> 3;
    const int swq = (q ^ (r0 & 7)) << 4;
#pragma unroll
    for (int p = 0; p < 4; p++) {
        const int r = r0 + p * 32;
        {
            const int gr = m0 + r;
            const bool ok = gr < M;
            cpa16(st + r * 128 + swq, A + (long)(ok ? gr : 0) * lda + k0 + q * 8, ok);
        }
        {
            const int gr = n0 + r;
            const bool ok = gr < N;
            cpa16(st + STAGE_A + r * 128 + swq,
                  B + (long)(ok ? gr : 0) * ldb + k0 + q * 8, ok);
        }
    }
}

// ---------------------------------------------------------------------------
// NT GEMM, fp16 in, fp32 accum. K specialized at compile time (KT K-tiles of
// 64); the kt loop fully unrolls -> constant stage addresses + cross-barrier
// software pipelining. Body otherwise identical to the proven R11 engine.
// outHalf=0: C float (+bias); 1: C half. fuseV: n >= 1536 -> vtOut transposed.
// ---------------------------------------------------------------------------
template<int KT>
__global__ __launch_bounds__(256, 2) void gemm_h(
    const __half* __restrict__ A, const __half* __restrict__ B,
    void* __restrict__ Cv, const float* __restrict__ bias,
    int M, int N, int lda, int ldb, int ldc,
    long sA, long sB, long sC, float alpha, int outHalf,
    int fuseV, __half* __restrict__ vtOut)
{
    extern __shared__ char smem[];
    const uint32_t sb = smem_u32(smem);
    const int tid = threadIdx.x;
    const int wid = tid >> 5, lane = tid & 31;
    const int wm = wid & 1, wn = wid >> 1;      // warp tile 64(m) x 32(n)

    const int bz = blockIdx.z;
    A += (long)bz * sA;  B += (long)bz * sB;
    const int m0 = blockIdx.y * 128;
    const int n0 = blockIdx.x * 128;

    const int a_row = lane & 15;
    const int a_co  = lane >> 4;
    const uint32_t a_base = (uint32_t)((wm * 64 + a_row) * 128 +
                                       ((a_co ^ (a_row & 7)) << 4));
    const int b_rowoff = ((lane >> 4) & 1) * 8 + (lane & 7);
    const int b_co     = (lane >> 3) & 1;
    const uint32_t b_base = (uint32_t)(STAGE_A + (wn * 32 + b_rowoff) * 128 +
                                       ((b_co ^ (b_rowoff & 7)) << 4));

    float acc[4][4][4];
#pragma unroll
    for (int i = 0; i < 4; i++)
#pragma unroll
        for (int j = 0; j < 4; j++)
#pragma unroll
            for (int r = 0; r < 4; r++) acc[i][j][r] = 0.f;

    fill_stage(A, B, M, N, lda, ldb, m0, n0, 0, sb, tid);
    asm volatile("cp.async.commit_group;" ::: "memory");
    if (KT > 1)
        fill_stage(A, B, M, N, lda, ldb, m0, n0, 64, sb + STAGE_BYTES, tid);
    asm volatile("cp.async.commit_group;" ::: "memory");

#pragma unroll
    for (int kt = 0; kt < KT; kt++) {
        asm volatile("cp.async.wait_group 1;" ::: "memory");
        __syncthreads();

        const uint32_t st = sb + (kt % NSTAGE) * STAGE_BYTES;

        uint32_t bf[2][2][4];                    // [buf][np][regs]
        ldsm4(st + b_base,        bf[0][0]);
        ldsm4(st + b_base + 2048, bf[0][1]);

#pragma unroll
        for (int s = 0; s < 4; s++) {
            const int cur = s & 1, nxt = cur ^ 1;
            if (s < 3) {                         // prefetch B for s+1
                const uint32_t kswn = (uint32_t)(2 * (s + 1)) << 4;
                const uint32_t bb2 = st + (b_base ^ kswn);
                ldsm4(bb2,        bf[nxt][0]);
                ldsm4(bb2 + 2048, bf[nxt][1]);
            }
            const uint32_t ksw = (uint32_t)(2 * s) << 4;
            const uint32_t ba = st + (a_base ^ ksw);
#pragma unroll
            for (int mtp = 0; mtp < 2; mtp++) {  // A in pairs (8 live regs)
                uint32_t af[2][4];
                ldsm4(ba + (2 * mtp) * 2048,     af[0]);
                ldsm4(ba + (2 * mtp + 1) * 2048, af[1]);
#pragma unroll
                for (int mi = 0; mi < 2; mi++) {
                    const int mt = 2 * mtp + mi;
#pragma unroll
                    for (int nt = 0; nt < 4; nt++)
                        mma16(acc[mt][nt], af[mi], &bf[cur][nt >> 1][(nt & 1) * 2]);
                }
            }
            if (s == 0) {                        // refill while s=1..3 compute
                const int fs = kt + 2;
                if (fs < KT)
                    fill_stage(A, B, M, N, lda, ldb, m0, n0, fs * 64,
                               sb + (fs % NSTAGE) * STAGE_BYTES, tid);
                asm volatile("cp.async.commit_group;" ::: "memory");
            }
        }
    }

    // epilogue
    const int r4 = lane >> 2, cp2 = (lane & 3) * 2;
    if (outHalf) {
        __half* C = (__half*)Cv + (long)bz * sC;
        const bool vec = ((ldc & 1) == 0);       // ldc odd -> scalar stores
#pragma unroll
        for (int mt = 0; mt < 4; mt++)
#pragma unroll
            for (int half_ = 0; half_ < 2; half_++) {
                const int m = m0 + wm * 64 + mt * 16 + r4 + half_ * 8;
                if (m >= M) continue;
                const long base = (long)m * ldc;
#pragma unroll
                for (int nt = 0; nt < 4; nt++) {
                    const int n = n0 + wn * 32 + nt * 8 + cp2;
                    if (n >= N) continue;
                    const float v0 = acc[mt][nt][half_ * 2 + 0] * alpha;
                    const float v1 = acc[mt][nt][half_ * 2 + 1] * alpha;
                    if (fuseV && n >= 1536) {
                        const int b = m / SEQ;
                        const int kk = m - b * SEQ;
                        __half* dst = vtOut + (long)b * DIM * SPAD
                                            + (long)(n - 1536) * SPAD + kk;
                        dst[0]    = __float2half_rn(v0);
                        dst[SPAD] = __float2half_rn(v1);
                    } else if (vec && (n + 1 < N)) {
                        *(__half2*)(C + base + n) = __floats2half2_rn(v0, v1);
                    } else {
                        C[base + n] = __float2half_rn(v0);
                        if (n + 1 < N) C[base + n + 1] = __float2half_rn(v1);
                    }
                }
            }
    } else {
        float* C = (float*)Cv + (long)bz * sC;
#pragma unroll
        for (int mt = 0; mt < 4; mt++)
#pragma unroll
            for (int half_ = 0; half_ < 2; half_++) {
                const int m = m0 + wm * 64 + mt * 16 + r4 + half_ * 8;
                if (m >= M) continue;
                const long base = (long)m * ldc;
#pragma unroll
                for (int nt = 0; nt < 4; nt++) {
                    const int n = n0 + wn * 32 + nt * 8 + cp2;
                    if (n >= N) continue;
                    float v0 = acc[mt][nt][half_ * 2 + 0] * alpha;
                    float v1 = acc[mt][nt][half_ * 2 + 1] * alpha;
                    if (bias) {
                        v0 += bias[n];
                        if (n + 1 < N) v1 += bias[n + 1];
                    }
                    if (((ldc & 1) == 0) && (n + 1 < N)) {
                        *(float2*)(C + base + n) = make_float2(v0, v1);
                    } else {
                        C[base + n] = v0;
                        if (n + 1 < N) C[base + n + 1] = v1;
                    }
                }
            }
    }
}

// ---------------- merged prologue: f2h x3 + vt pad zero ----------------
#define N1 ((long)ROWS * DIM / 4)
#define N2 ((long)QKVD * DIM / 4)
#define N3 ((long)DIM * DIM / 4)
#define N4 ((long)BB * DIM * 8)

__device__ __forceinline__ void cvt4(const float* __restrict__ in,
                                     __half* __restrict__ out, long i) {
    const float4 v = *(const float4*)(in + i * 4);
    *(__half2*)(out + i * 4)     = __floats2half2_rn(v.x, v.y);
    *(__half2*)(out + i * 4 + 2) = __floats2half2_rn(v.z, v.w);
}

__global__ void prologue_kernel(const float* __restrict__ x,
                                const float* __restrict__ wq,
                                const float* __restrict__ wp,
                                __half* __restrict__ xh,
                                __half* __restrict__ wqh,
                                __half* __restrict__ wph,
                                __half* __restrict__ vt) {
    long i = (long)blockIdx.x * blockDim.x + threadIdx.x;
    if (i < N1) { cvt4(x, xh, i); return; }
    i -= N1;
    if (i < N2) { cvt4(wq, wqh, i); return; }
    i -= N2;
    if (i < N3) { cvt4(wp, wph, i); return; }
    i -= N3;
    if (i < N4) {
        const long rc = i >> 3, j = i & 7;       // pad k in [576,640)
        *(float4*)(vt + rc * SPAD + 576 + j * 8) =
            make_float4(0.f, 0.f, 0.f, 0.f);
    }
}

// ---------------- softmax: one warp per row, barrier-free -------------------
__global__ __launch_bounds__(256) void softmax_kernel(
    const float* __restrict__ S, __half* __restrict__ P, float* __restrict__ tok)
{
    const int row  = (blockIdx.x << 3) | (threadIdx.x >> 5);
    const int lane = threadIdx.x & 31;
    const float* p = S + (long)row * SPAD;
    __half* o = P + (long)row * SPAD;

    float4 v[5];
    float m = -1e30f;
#pragma unroll
    for (int j = 0; j < 5; j++) {
        const int c0 = (lane + (j << 5)) << 2;
        float4 t = *(const float4*)(p + c0);
        t.x = (c0 + 0 < SEQ) ? t.x : -1e30f;
        t.y = (c0 + 1 < SEQ) ? t.y : -1e30f;
        t.z = (c0 + 2 < SEQ) ? t.z : -1e30f;
        t.w = (c0 + 3 < SEQ) ? t.w : -1e30f;
        v[j] = t;
        m = fmaxf(m, fmaxf(fmaxf(t.x, t.y), fmaxf(t.z, t.w)));
    }
#pragma unroll
    for (int off = 16; off > 0; off >>= 1)
        m = fmaxf(m, __shfl_xor_sync(0xFFFFFFFFu, m, off));

    float sum = 0.f;
#pragma unroll
    for (int j = 0; j < 5; j++) {
        v[j].x = __expf(v[j].x - m);
        v[j].y = __expf(v[j].y - m);
        v[j].z = __expf(v[j].z - m);
        v[j].w = __expf(v[j].w - m);
        sum += (v[j].x + v[j].y) + (v[j].z + v[j].w);
    }
#pragma unroll
    for (int off = 16; off > 0; off >>= 1)
        sum += __shfl_xor_sync(0xFFFFFFFFu, sum, off);
    const float inv = 1.0f / sum;

#pragma unroll
    for (int j = 0; j < 5; j++) {
        const int c0 = (lane + (j << 5)) << 2;
        *(__half2*)(o + c0)     = __floats2half2_rn(v[j].x * inv, v[j].y * inv);
        *(__half2*)(o + c0 + 2) = __floats2half2_rn(v[j].z * inv, v[j].w * inv);
    }

    if ((row % SEQ) == 0) {                      // token-attn extraction
        const int b = row / SEQ;
        float* t = tok + (long)b * (SEQ - 1);
#pragma unroll
        for (int j = 0; j < 5; j++) {
            const int c0 = (lane + (j << 5)) << 2;
            const float xs[4] = {v[j].x * inv, v[j].y * inv,
                                 v[j].z * inv, v[j].w * inv};
#pragma unroll
            for (int q = 0; q < 4; q++) {
                const int c = c0 + q;
                if (c >= 1 && c < SEQ) t[c - 1] = xs[q];
            }
        }
    }
}

// ---------------------------------------------------------------------------
extern "C" void kernel_launch(void* const* d_in, const int* in_sizes, int n_in,
                              void* d_out, int out_size)
{
    const float* x      = (const float*)d_in[0];
    const float* w_qkv  = (const float*)d_in[1];
    const float* w_proj = (const float*)d_in[2];
    const float* b_proj = (const float*)d_in[3];
    float* out = (float*)d_out;
    float* tok = out + (size_t)ROWS * DIM;

    __half *xh, *wqh, *wph, *qkvh, *p, *vt, *yt;
    float *s;
    cudaGetSymbolAddress((void**)&xh,   g_xh);
    cudaGetSymbolAddress((void**)&wqh,  g_wqh);
    cudaGetSymbolAddress((void**)&wph,  g_wph);
    cudaGetSymbolAddress((void**)&qkvh, g_qkvh);
    cudaGetSymbolAddress((void**)&s,    g_s);
    cudaGetSymbolAddress((void**)&p,    g_p);
    cudaGetSymbolAddress((void**)&vt,   g_vt);
    cudaGetSymbolAddress((void**)&yt,   g_yt);

    cudaFuncSetAttribute(gemm_h<12>, cudaFuncAttributeMaxDynamicSharedMemorySize, TC_SMEM);
    cudaFuncSetAttribute(gemm_h<10>, cudaFuncAttributeMaxDynamicSharedMemorySize, TC_SMEM);

    const float scale = 1.0f / sqrtf((float)DIM);

    // 0) merged prologue
    {
        const long total = N1 + N2 + N3 + N4;
        prologue_kernel<<<(int)((total + 255) / 256), 256>>>(
            x, w_qkv, w_proj, xh, wqh, wph, vt);
    }

    // 1) QKV: K=768 -> KT=12 (half out; V columns written transposed into vt)
    gemm_h<12><<<dim3(QKVD / 128, (ROWS + 127) / 128, 1), 256, TC_SMEM>>>(
        xh, wqh, qkvh, nullptr, ROWS, QKVD, DIM, DIM, QKVD,
        0, 0, 0, 1.0f, 1, 1, vt);

    // 2) S = scale * Q K^T: K=768 -> KT=12 (float out, ldc=SPAD even)
    gemm_h<12><<<dim3((SEQ + 127) / 128, (SEQ + 127) / 128, BB), 256, TC_SMEM>>>(
        qkvh, qkvh + DIM, s, nullptr, SEQ, SEQ, QKVD, QKVD, SPAD,
        (long)SEQ * QKVD, (long)SEQ * QKVD, (long)SEQ * SPAD, scale, 0, 0, nullptr);

    // 3) softmax -> fp16 P
    softmax_kernel<<<ROWS / 8, 256>>>(s, p, tok);

    // 4) yt = Vt @ P^T: K=640 -> KT=10 (half out, ldc=SEQ odd -> scalar path)
    gemm_h<10><<<dim3((SEQ + 127) / 128, DIM / 128, BB), 256, TC_SMEM>>>(
        vt, p, yt, nullptr, DIM, SEQ, SPAD, SPAD, SEQ,
        (long)DIM * SPAD, (long)SEQ * SPAD, (long)DIM * SEQ, 1.0f, 1, 0, nullptr);

    // 5) out = Y2 @ Wproj^T + bias: K=768 -> KT=12 (float out)
    gemm_h<12><<<dim3(DIM / 128, (ROWS + 127) / 128, 1), 256, TC_SMEM>>>(
        yt, wph, out, b_proj, ROWS, DIM, DIM, DIM, DIM,
        0, 0, 0, 1.0f, 0, 0, nullptr);
}